// round 12
// baseline (speedup 1.0000x reference)
#include <cuda_runtime.h>
#include <cuda_bf16.h>
#include <cstdint>
#include <math.h>

#define Bb   2
#define Nn   2048
#define Cc   768
#define NH   12
#define HD   64
#define HW   64
#define WW   128

// ================= mma.sync / ldmatrix helpers (sm_80+ base ISA) =================
__device__ __forceinline__ uint32_t smem_u32(const void* p) {
    uint32_t a;
    asm("{ .reg .u64 t; cvta.to.shared.u64 t, %1; cvt.u32.u64 %0, t; }" : "=r"(a) : "l"(p));
    return a;
}
__device__ __forceinline__ void ldsm4(uint32_t* r, uint32_t addr) {
    asm volatile("ldmatrix.sync.aligned.m8n8.x4.shared.b16 {%0,%1,%2,%3}, [%4];"
                 : "=r"(r[0]), "=r"(r[1]), "=r"(r[2]), "=r"(r[3]) : "r"(addr));
}
__device__ __forceinline__ void ldsm4_t(uint32_t* r, uint32_t addr) {
    asm volatile("ldmatrix.sync.aligned.m8n8.x4.trans.shared.b16 {%0,%1,%2,%3}, [%4];"
                 : "=r"(r[0]), "=r"(r[1]), "=r"(r[2]), "=r"(r[3]) : "r"(addr));
}
__device__ __forceinline__ void mma_bf16(float* c, const uint32_t* a, const uint32_t* b) {
    asm volatile(
        "mma.sync.aligned.m16n8k16.row.col.f32.bf16.bf16.f32 "
        "{%0,%1,%2,%3}, {%4,%5,%6,%7}, {%8,%9}, {%0,%1,%2,%3};"
        : "+f"(c[0]), "+f"(c[1]), "+f"(c[2]), "+f"(c[3])
        : "r"(a[0]), "r"(a[1]), "r"(a[2]), "r"(a[3]), "r"(b[0]), "r"(b[1]));
}
__device__ __forceinline__ void splitpack(float x, float y, uint32_t& hi, uint32_t& lo) {
    __nv_bfloat16 hx = __float2bfloat16(x), hy = __float2bfloat16(y);
    float lx = x - __bfloat162float(hx), ly = y - __bfloat162float(hy);
    __nv_bfloat16 ex = __float2bfloat16(lx), ey = __float2bfloat16(ly);
    hi = (uint32_t)(*(uint16_t*)&hx) | ((uint32_t)(*(uint16_t*)&hy) << 16);
    lo = (uint32_t)(*(uint16_t*)&ex) | ((uint32_t)(*(uint16_t*)&ey) << 16);
}

// ================= scratch (total = 88.1 MB, identical to R7's passing footprint) ===
__device__ uint16_t g_qhi[Bb * NH * Nn * HD];   // bf16, scale 0.125 folded
__device__ uint16_t g_qlo[Bb * NH * Nn * HD];
__device__ uint16_t g_khi[Bb * NH * Nn * HD];
__device__ uint16_t g_klo[Bb * NH * Nn * HD];
__device__ uint16_t g_vhi[Bb * NH * Nn * HD];
__device__ uint16_t g_vlo[Bb * NH * Nn * HD];
// Aliased buffer: steps 2-3 it holds pre-split x (bf16 hi | bf16 lo);
// step 4 attention overwrites it as fp32 o; step 5 proj reads fp32 o.
#define XELEMS (Bb * Nn * Cc)
__device__ __align__(16) unsigned char g_obuf[(size_t)XELEMS * 4];
__device__ float g_ws[Bb * Nn];

// ================= wind strength =================
__global__ void wind_kernel(const float* __restrict__ u, const float* __restrict__ v) {
    int idx = blockIdx.x * blockDim.x + threadIdx.x;
    if (idx >= Bb * Nn) return;
    int b = idx / Nn, n = idx - b * Nn;
    int ph = n >> 6, pw = n & 63;
    const float* ub = u + b * HW * WW;
    const float* vb = v + b * HW * WW;
    float s = 0.f;
#pragma unroll
    for (int di = 0; di < 2; di++)
#pragma unroll
        for (int dj = 0; dj < 2; dj++) {
            int r = 2 * ph + di, c = 2 * pw + dj;
            float uu = ub[r * WW + c];
            float vv = vb[r * WW + c];
            s += sqrtf(uu * uu + vv * vv + 1e-8f);
        }
    g_ws[idx] = 0.25f * s;
}

// ================= x -> bf16 hi/lo split into aliased buffer =================
__global__ void split_x_kernel(const float* __restrict__ src) {
    int i = blockIdx.x * blockDim.x + threadIdx.x;
    if (i >= XELEMS / 4) return;
    uint16_t* hi = (uint16_t*)g_obuf;
    uint16_t* lo = (uint16_t*)(g_obuf + (size_t)XELEMS * 2);
    float4 v = ((const float4*)src)[i];
    uint32_t h0, l0, h1, l1;
    splitpack(v.x, v.y, h0, l0);
    splitpack(v.z, v.w, h1, l1);
    ((uint2*)hi)[i] = make_uint2(h0, h1);
    ((uint2*)lo)[i] = make_uint2(l0, l1);
}

// ================= bf16-split tensor-core GEMM: C = A @ B^T =================
// 128x128 tile, BK=32, 256 thr (2x4 warps, warp tile 64x32), 24 stages.
// R7-proven skeleton. B (weights) converted in-kernel from fp32.
// MODE 0: A = pre-split x (pure uint4 copies); scatter into g_q/g_k/g_v hi+lo.
// MODE 1: A = fp32 o in g_obuf, converted in-kernel; out = Cout + bias.
#define ASTR 40   // bf16 elems per smem row (80 B): conflict-free ldmatrix phases

template <int MODE>
__global__ void __launch_bounds__(256, 2)
mma_gemm(const float* __restrict__ Bm, const float* __restrict__ bias,
         float* __restrict__ Cout) {
    __shared__ __align__(16) uint16_t sAhi[128 * ASTR];
    __shared__ __align__(16) uint16_t sAlo[128 * ASTR];
    __shared__ __align__(16) uint16_t sBhi[128 * ASTR];
    __shared__ __align__(16) uint16_t sBlo[128 * ASTR];

    int tid = threadIdx.x, wid = tid >> 5, lane = tid & 31;
    int wm = wid & 1;
    int wn = wid >> 1;
    int bm0 = blockIdx.y * 128;
    int bn0 = blockIdx.x * 128;

    uint32_t ahi_b = smem_u32(sAhi), alo_b = smem_u32(sAlo);
    uint32_t bhi_b = smem_u32(sBhi), blo_b = smem_u32(sBlo);

    float acc[4][4][4];
#pragma unroll
    for (int i = 0; i < 4; i++)
#pragma unroll
        for (int j = 0; j < 4; j++)
#pragma unroll
            for (int r = 0; r < 4; r++) acc[i][j][r] = 0.f;

    for (int s = 0; s < Cc / 32; s++) {
        int k0 = s * 32;
        // ---- prefetch stage into registers (overlaps with prior compute) ----
        float4 bv[4];
#pragma unroll
        for (int i = 0; i < 4; i++) {
            int idx = tid + 256 * i;
            int row = idx >> 3, c4 = idx & 7;
            bv[i] = *(const float4*)(Bm + (size_t)(bn0 + row) * Cc + k0 + c4 * 4);
        }
        uint4 xa[2], xl[2];
        float4 av[4];
        if (MODE == 0) {
            const uint16_t* xhi = (const uint16_t*)g_obuf;
            const uint16_t* xlo = (const uint16_t*)(g_obuf + (size_t)XELEMS * 2);
#pragma unroll
            for (int i = 0; i < 2; i++) {
                int idx = tid + 256 * i;
                int row = idx >> 2, c = idx & 3;
                size_t ga = (size_t)(bm0 + row) * Cc + k0 + c * 8;
                xa[i] = *(const uint4*)(xhi + ga);
                xl[i] = *(const uint4*)(xlo + ga);
            }
        } else {
            const float* Af = (const float*)g_obuf;
#pragma unroll
            for (int i = 0; i < 4; i++) {
                int idx = tid + 256 * i;
                int row = idx >> 3, c4 = idx & 7;
                av[i] = *(const float4*)(Af + (size_t)(bm0 + row) * Cc + k0 + c4 * 4);
            }
        }
        __syncthreads();   // previous stage's compute done before overwrite

        // ---- store to smem (convert where needed) ----
#pragma unroll
        for (int i = 0; i < 4; i++) {
            int idx = tid + 256 * i;
            int row = idx >> 3, c4 = idx & 7;
            int base = row * ASTR + c4 * 4;
            float vb[4] = { bv[i].x, bv[i].y, bv[i].z, bv[i].w };
#pragma unroll
            for (int e = 0; e < 4; e++) {
                __nv_bfloat16 hh = __float2bfloat16(vb[e]);
                __nv_bfloat16 ll = __float2bfloat16(vb[e] - __bfloat162float(hh));
                sBhi[base + e] = *(uint16_t*)&hh;
                sBlo[base + e] = *(uint16_t*)&ll;
            }
        }
        if (MODE == 0) {
#pragma unroll
            for (int i = 0; i < 2; i++) {
                int idx = tid + 256 * i;
                int row = idx >> 2, c = idx & 3;
                int off = row * ASTR + c * 8;
                *(uint4*)&sAhi[off] = xa[i];
                *(uint4*)&sAlo[off] = xl[i];
            }
        } else {
#pragma unroll
            for (int i = 0; i < 4; i++) {
                int idx = tid + 256 * i;
                int row = idx >> 3, c4 = idx & 7;
                int base = row * ASTR + c4 * 4;
                float va[4] = { av[i].x, av[i].y, av[i].z, av[i].w };
#pragma unroll
                for (int e = 0; e < 4; e++) {
                    __nv_bfloat16 hh = __float2bfloat16(va[e]);
                    __nv_bfloat16 ll = __float2bfloat16(va[e] - __bfloat162float(hh));
                    sAhi[base + e] = *(uint16_t*)&hh;
                    sAlo[base + e] = *(uint16_t*)&ll;
                }
            }
        }
        __syncthreads();

#pragma unroll
        for (int ks = 0; ks < 2; ks++) {
            uint32_t ah[4][4], al[4][4], bh[2][4], bl[2][4];
            {
                int r = wm * 64 + (lane & 15);
                uint32_t off = (uint32_t)(r * 80 + ks * 32 + ((lane >> 4) << 4));
#pragma unroll
                for (int mf = 0; mf < 4; mf++) {
                    ldsm4(ah[mf], ahi_b + off + mf * 16 * 80);
                    ldsm4(al[mf], alo_b + off + mf * 16 * 80);
                }
            }
            {
                int g = lane >> 3;
                int nr = wn * 32 + ((g >> 1) << 3) + (lane & 7);
                uint32_t off = (uint32_t)(nr * 80 + ks * 32 + ((g & 1) << 4));
#pragma unroll
                for (int np = 0; np < 2; np++) {
                    ldsm4(bh[np], bhi_b + off + np * 16 * 80);
                    ldsm4(bl[np], blo_b + off + np * 16 * 80);
                }
            }
#pragma unroll
            for (int mf = 0; mf < 4; mf++)
#pragma unroll
                for (int nf = 0; nf < 4; nf++) {
                    const uint32_t* bhp = &bh[nf >> 1][(nf & 1) * 2];
                    const uint32_t* blp = &bl[nf >> 1][(nf & 1) * 2];
                    mma_bf16(acc[mf][nf], ah[mf], bhp);
                    mma_bf16(acc[mf][nf], ah[mf], blp);
                    mma_bf16(acc[mf][nf], al[mf], bhp);
                }
        }
    }

    // ---------------- epilogue ----------------
#pragma unroll
    for (int mf = 0; mf < 4; mf++) {
#pragma unroll
        for (int nf = 0; nf < 4; nf++) {
#pragma unroll
            for (int half = 0; half < 2; half++) {
                int row = bm0 + wm * 64 + mf * 16 + (lane >> 2) + half * 8;
                int col = bn0 + wn * 32 + nf * 8 + (lane & 3) * 2;
                float v0 = acc[mf][nf][half * 2];
                float v1 = acc[mf][nf][half * 2 + 1];
                if (MODE == 0) {
                    int b_ = row >> 11;
                    int n_ = row & 2047;
                    int which = col / Cc;
                    int rem = col - which * Cc;
                    int h_ = rem >> 6;
                    int d_ = rem & 63;
                    size_t idx = (((size_t)(b_ * NH + h_) * Nn + n_) << 6) + d_;
                    uint16_t* hiA;
                    uint16_t* loA;
                    if (which == 0) { v0 *= 0.125f; v1 *= 0.125f; hiA = g_qhi; loA = g_qlo; }
                    else if (which == 1) { hiA = g_khi; loA = g_klo; }
                    else { hiA = g_vhi; loA = g_vlo; }
                    uint32_t hi, lo;
                    splitpack(v0, v1, hi, lo);
                    *(uint32_t*)&hiA[idx] = hi;
                    *(uint32_t*)&loA[idx] = lo;
                } else {
                    float* dst = Cout + (size_t)row * Cc + col;
                    *(float2*)dst = make_float2(v0 + bias[col], v1 + bias[col + 1]);
                }
            }
        }
    }
}

// ================= tensor-core flash attention with topo/wind bias =================
// (byte-identical logic to the R7 passing version; g_o -> (float*)g_obuf)
__device__ __forceinline__ float biasf(float ej, float wj, float ei, float wi,
                                       float alpha, float beta) {
    float diff = (ej - ei) * 0.001f;
    float bv = -alpha * fmaxf(diff, 0.f);
    float wa = 0.5f * (wi + wj);
    float mod = 1.f - beta * __fdividef(1.f, 1.f + __expf(5.f - wa));
    return fmaxf(bv * mod, -10.f);
}

__global__ void __launch_bounds__(256)
attn_mma(const float* __restrict__ elev,
         const float* __restrict__ alpha_p, const float* __restrict__ beta_p) {
    __shared__ __align__(16) uint16_t sbuf[18432];
    __shared__ float ejs[64], wjs[64];

    int tid = threadIdx.x, w = tid >> 5, L = tid & 31;
    int i0 = blockIdx.x * 128, bh = blockIdx.y;
    int b = bh / NH, h = bh - b * NH;
    float alpha = *alpha_p, beta = *beta_p;
    uint32_t sb32 = smem_u32(sbuf);
    float* g_o = (float*)g_obuf;

    // ---- stage Q tile (hi/lo) and extract a-frags ----
    {
        const uint4* q0 = (const uint4*)(g_qhi + ((size_t)bh * Nn + i0) * HD);
        const uint4* q1 = (const uint4*)(g_qlo + ((size_t)bh * Nn + i0) * HD);
#pragma unroll
        for (int it = 0; it < 8; it++) {
            int id = tid + 256 * it;
            int arr = id >> 10, rid = (id >> 3) & 127, c = id & 7;
            uint4 vv = (arr == 0) ? q0[rid * 8 + c] : q1[rid * 8 + c];
            *(uint4*)&sbuf[arr * 9216 + rid * 72 + c * 8] = vv;
        }
    }
    __syncthreads();
    uint32_t qh[4][4], ql[4][4];
#pragma unroll
    for (int kc = 0; kc < 4; kc++) {
        uint32_t off = (uint32_t)(((16 * w + (L & 15)) * 72 + kc * 16 + ((L >> 4) << 3)) * 2);
        ldsm4(qh[kc], sb32 + off);
        ldsm4(ql[kc], sb32 + 18432 + off);
    }
    __syncthreads();

    int r0 = i0 + 16 * w + (L >> 2);
    float ei0 = elev[b * Nn + r0],     ei1 = elev[b * Nn + r0 + 8];
    float wi0 = g_ws[b * Nn + r0],     wi1 = g_ws[b * Nn + r0 + 8];

    float o[8][4];
#pragma unroll
    for (int i = 0; i < 8; i++)
#pragma unroll
        for (int j = 0; j < 4; j++) o[i][j] = 0.f;
    float l0 = 0.f, l1 = 0.f;

    const uint4* kp0 = (const uint4*)(g_khi + ((size_t)bh * Nn) * HD);
    const uint4* kp1 = (const uint4*)(g_klo + ((size_t)bh * Nn) * HD);
    const uint4* vp0 = (const uint4*)(g_vhi + ((size_t)bh * Nn) * HD);
    const uint4* vp1 = (const uint4*)(g_vlo + ((size_t)bh * Nn) * HD);

    for (int j0 = 0; j0 < Nn; j0 += 64) {
        int jchunk = j0 * 8;
#pragma unroll
        for (int it = 0; it < 8; it++) {
            int id = tid + 256 * it;
            int arr = id >> 9, rid = (id >> 3) & 63, c = id & 7;
            const uint4* sp = (arr == 0) ? kp0 : (arr == 1) ? kp1 : (arr == 2) ? vp0 : vp1;
            uint4 vv = sp[jchunk + rid * 8 + c];
            *(uint4*)&sbuf[arr * 4608 + rid * 72 + c * 8] = vv;
        }
        if (tid < 64) {
            ejs[tid] = elev[b * Nn + j0 + tid];
            wjs[tid] = g_ws[b * Nn + j0 + tid];
        }
        __syncthreads();

        float sc[8][4];
#pragma unroll
        for (int i = 0; i < 8; i++)
#pragma unroll
            for (int j = 0; j < 4; j++) sc[i][j] = 0.f;

        // ---- QK^T ----
        int g = L >> 3;
#pragma unroll
        for (int kc = 0; kc < 4; kc++) {
#pragma unroll
            for (int nf2 = 0; nf2 < 4; nf2++) {
                uint32_t off = (uint32_t)(((nf2 * 16 + (g >> 1) * 8 + (L & 7)) * 72
                                          + kc * 16 + (g & 1) * 8) * 2);
                uint32_t bh2[4], bl2[4];
                ldsm4(bh2, sb32 + off);
                ldsm4(bl2, sb32 + 9216 + off);
                mma_bf16(sc[nf2 * 2],     qh[kc], &bh2[0]);
                mma_bf16(sc[nf2 * 2],     qh[kc], &bl2[0]);
                mma_bf16(sc[nf2 * 2],     ql[kc], &bh2[0]);
                mma_bf16(sc[nf2 * 2 + 1], qh[kc], &bh2[2]);
                mma_bf16(sc[nf2 * 2 + 1], qh[kc], &bl2[2]);
                mma_bf16(sc[nf2 * 2 + 1], ql[kc], &bh2[2]);
            }
        }

        // ---- bias + exp ----
#pragma unroll
        for (int nf = 0; nf < 8; nf++) {
            int jl = nf * 8 + (L & 3) * 2;
            float e0 = ejs[jl], e1 = ejs[jl + 1];
            float x0 = wjs[jl], x1 = wjs[jl + 1];
            sc[nf][0] = __expf(sc[nf][0] + biasf(e0, x0, ei0, wi0, alpha, beta));
            sc[nf][1] = __expf(sc[nf][1] + biasf(e1, x1, ei0, wi0, alpha, beta));
            sc[nf][2] = __expf(sc[nf][2] + biasf(e0, x0, ei1, wi1, alpha, beta));
            sc[nf][3] = __expf(sc[nf][3] + biasf(e1, x1, ei1, wi1, alpha, beta));
            l0 += sc[nf][0] + sc[nf][1];
            l1 += sc[nf][2] + sc[nf][3];
        }

        // ---- P @ V ----
#pragma unroll
        for (int jc = 0; jc < 4; jc++) {
            uint32_t phi[4], plo[4];
            splitpack(sc[2 * jc][0],     sc[2 * jc][1],     phi[0], plo[0]);
            splitpack(sc[2 * jc][2],     sc[2 * jc][3],     phi[1], plo[1]);
            splitpack(sc[2 * jc + 1][0], sc[2 * jc + 1][1], phi[2], plo[2]);
            splitpack(sc[2 * jc + 1][2], sc[2 * jc + 1][3], phi[3], plo[3]);
#pragma unroll
            for (int nd2 = 0; nd2 < 4; nd2++) {
                uint32_t off = (uint32_t)(((jc * 16 + (g & 1) * 8 + (L & 7)) * 72
                                          + nd2 * 16 + (g >> 1) * 8) * 2);
                uint32_t vh2[4], vl2[4];
                ldsm4_t(vh2, sb32 + 18432 + off);
                ldsm4_t(vl2, sb32 + 27648 + off);
                mma_bf16(o[nd2 * 2],     phi, &vh2[0]);
                mma_bf16(o[nd2 * 2],     phi, &vl2[0]);
                mma_bf16(o[nd2 * 2],     plo, &vh2[0]);
                mma_bf16(o[nd2 * 2 + 1], phi, &vh2[2]);
                mma_bf16(o[nd2 * 2 + 1], phi, &vl2[2]);
                mma_bf16(o[nd2 * 2 + 1], plo, &vh2[2]);
            }
        }
        __syncthreads();
    }

    l0 += __shfl_xor_sync(0xffffffffu, l0, 1);
    l0 += __shfl_xor_sync(0xffffffffu, l0, 2);
    l1 += __shfl_xor_sync(0xffffffffu, l1, 1);
    l1 += __shfl_xor_sync(0xffffffffu, l1, 2);
    float inv0 = 1.f / l0, inv1 = 1.f / l1;

#pragma unroll
    for (int nf = 0; nf < 8; nf++) {
        int d = h * 64 + nf * 8 + (L & 3) * 2;
        *(float2*)&g_o[((size_t)(b * Nn + r0)) * Cc + d] =
            make_float2(o[nf][0] * inv0, o[nf][1] * inv0);
        *(float2*)&g_o[((size_t)(b * Nn + r0 + 8)) * Cc + d] =
            make_float2(o[nf][2] * inv1, o[nf][3] * inv1);
    }
}

extern "C" void kernel_launch(void* const* d_in, const int* in_sizes, int n_in,
                              void* d_out, int out_size) {
    const float* x     = (const float*)d_in[0];
    const float* elev  = (const float*)d_in[1];
    const float* u     = (const float*)d_in[2];
    const float* v     = (const float*)d_in[3];
    const float* Wqkv  = (const float*)d_in[4];
    const float* Wproj = (const float*)d_in[5];
    const float* bproj = (const float*)d_in[6];
    const float* alpha = (const float*)d_in[7];
    const float* beta  = (const float*)d_in[8];
    float* out = (float*)d_out;

    (void)in_sizes; (void)n_in; (void)out_size;

    // 1. wind strength
    wind_kernel<<<(Bb * Nn + 255) / 256, 256>>>(u, v);

    // 2. split x into the aliased buffer (hi | lo)
    split_x_kernel<<<(XELEMS / 4 + 255) / 256, 256>>>(x);

    // 3. QKV projection (A = pre-split x: pure copies; B converted in-kernel)
    {
        dim3 grid(3 * Cc / 128, (Bb * Nn) / 128);   // (18, 32)
        mma_gemm<0><<<grid, 256>>>(Wqkv, nullptr, nullptr);
    }

    // 4. tensor-core flash attention (R7-proven; overwrites buffer as fp32 o)
    {
        dim3 grid(Nn / 128, Bb * NH);               // (16, 24)
        attn_mma<<<grid, 256>>>(elev, alpha, beta);
    }

    // 5. output projection (A = fp32 o converted in-kernel; B converted in-kernel)
    {
        dim3 grid(Cc / 128, (Bb * Nn) / 128);       // (6, 32)
        mma_gemm<1><<<grid, 256>>>(Wproj, bproj, out);
    }
}

// round 15
// speedup vs baseline: 1.0294x; 1.0294x over previous
#include <cuda_runtime.h>
#include <cuda_bf16.h>
#include <cstdint>
#include <math.h>

// Problem shape constants
#define Bb   2
#define Nn   2048
#define Cc   768
#define NH   12
#define HD   64
#define HW   64
#define WW   128

// ========== mma.sync / ldmatrix wrappers (sm_80+ base ISA, valid on sm_100) ==========
__device__ __forceinline__ uint32_t smem_cast(const void* p) {
    uint32_t a;
    asm("{ .reg .u64 t; cvta.to.shared.u64 t, %1; cvt.u32.u64 %0, t; }" : "=r"(a) : "l"(p));
    return a;
}
__device__ __forceinline__ void ldm_x4(uint32_t* r, uint32_t addr) {
    asm volatile("ldmatrix.sync.aligned.m8n8.x4.shared.b16 {%0,%1,%2,%3}, [%4];"
                 : "=r"(r[0]), "=r"(r[1]), "=r"(r[2]), "=r"(r[3]) : "r"(addr));
}
__device__ __forceinline__ void ldm_x4t(uint32_t* r, uint32_t addr) {
    asm volatile("ldmatrix.sync.aligned.m8n8.x4.trans.shared.b16 {%0,%1,%2,%3}, [%4];"
                 : "=r"(r[0]), "=r"(r[1]), "=r"(r[2]), "=r"(r[3]) : "r"(addr));
}
__device__ __forceinline__ void hmma(float* c, const uint32_t* a, const uint32_t* b) {
    asm volatile(
        "mma.sync.aligned.m16n8k16.row.col.f32.bf16.bf16.f32 "
        "{%0,%1,%2,%3}, {%4,%5,%6,%7}, {%8,%9}, {%0,%1,%2,%3};"
        : "+f"(c[0]), "+f"(c[1]), "+f"(c[2]), "+f"(c[3])
        : "r"(a[0]), "r"(a[1]), "r"(a[2]), "r"(a[3]), "r"(b[0]), "r"(b[1]));
}
// 2-term bf16 split of an fp32 pair, packed into two b32 lanes
__device__ __forceinline__ void bsplit2(float x, float y, uint32_t& hi, uint32_t& lo) {
    __nv_bfloat16 hx = __float2bfloat16(x), hy = __float2bfloat16(y);
    float rx = x - __bfloat162float(hx), ry = y - __bfloat162float(hy);
    __nv_bfloat16 ex = __float2bfloat16(rx), ey = __float2bfloat16(ry);
    hi = (uint32_t)(*(uint16_t*)&hx) | ((uint32_t)(*(uint16_t*)&hy) << 16);
    lo = (uint32_t)(*(uint16_t*)&ex) | ((uint32_t)(*(uint16_t*)&ey) << 16);
}
__device__ __forceinline__ float fast_ex2(float x) {
    float r; asm("ex2.approx.f32 %0, %1;" : "=f"(r) : "f"(x)); return r;
}
__device__ __forceinline__ float fast_rcp(float x) {
    float r; asm("rcp.approx.f32 %0, %1;" : "=f"(r) : "f"(x)); return r;
}

// ========== device scratch: 88.1 MB total (within the confirmed globals budget) ======
__device__ uint16_t g_qhi[Bb * NH * Nn * HD];   // bf16; 0.125*log2(e) folded in
__device__ uint16_t g_qlo[Bb * NH * Nn * HD];
__device__ uint16_t g_khi[Bb * NH * Nn * HD];
__device__ uint16_t g_klo[Bb * NH * Nn * HD];
__device__ uint16_t g_vhi[Bb * NH * Nn * HD];
__device__ uint16_t g_vlo[Bb * NH * Nn * HD];
// Time-multiplexed buffer. Phase 1 (steps 2-3): pre-split x as [bf16 hi | bf16 lo].
// Phase 2 (steps 4-5): fp32 attention output o. Lifetimes are disjoint; each graph
// replay regenerates both phases, so results are replay-deterministic.
#define XELEMS (Bb * Nn * Cc)
__device__ __align__(16) unsigned char g_obuf[(size_t)XELEMS * 4];
__device__ float g_ws[Bb * Nn];

// ========== wind strength: 2x2 avg-pool of wind magnitude ==========
__global__ void wind_kernel(const float* __restrict__ u, const float* __restrict__ v) {
    int idx = blockIdx.x * blockDim.x + threadIdx.x;
    if (idx >= Bb * Nn) return;
    int b = idx / Nn, n = idx - b * Nn;
    int ph = n >> 6, pw = n & 63;
    const float* ub = u + b * HW * WW;
    const float* vb = v + b * HW * WW;
    float s = 0.f;
#pragma unroll
    for (int di = 0; di < 2; di++)
#pragma unroll
        for (int dj = 0; dj < 2; dj++) {
            int r = 2 * ph + di, c = 2 * pw + dj;
            float uu = ub[r * WW + c];
            float vv = vb[r * WW + c];
            s += sqrtf(uu * uu + vv * vv + 1e-8f);
        }
    g_ws[idx] = 0.25f * s;
}

// ========== x -> bf16 hi/lo, written into phase-1 of g_obuf ==========
__global__ void split_x_kernel(const float* __restrict__ src) {
    int i = blockIdx.x * blockDim.x + threadIdx.x;
    if (i >= XELEMS / 4) return;
    uint16_t* hi = (uint16_t*)g_obuf;
    uint16_t* lo = (uint16_t*)(g_obuf + (size_t)XELEMS * 2);
    float4 v = ((const float4*)src)[i];
    uint32_t h0, l0, h1, l1;
    bsplit2(v.x, v.y, h0, l0);
    bsplit2(v.z, v.w, h1, l1);
    ((uint2*)hi)[i] = make_uint2(h0, h1);
    ((uint2*)lo)[i] = make_uint2(l0, l1);
}

// ========== bf16-split tensor-core GEMM, C = A @ B^T ==========
// 128x128 CTA tile, BK=32, 256 threads (2x4 warps; 64x32 warp tile), 24 K-stages.
// D = Ahi*Bhi + Ahi*Blo + Alo*Bhi, fp32 accumulate (3-term split ~ fp32 accuracy).
// MODE 0: A = phase-1 pre-split x (raw uint4 copies), scatter q/k/v hi+lo.
// MODE 1: A = phase-2 fp32 o, converted in-kernel; writes Cout + bias.
#define ASTR 40   // smem row stride in bf16 elems (80 B) -> conflict-free ldmatrix

template <int MODE>
__global__ void __launch_bounds__(256, 2)
mma_gemm(const float* __restrict__ Bm, const float* __restrict__ bias,
         float* __restrict__ Cout) {
    __shared__ __align__(16) uint16_t sAhi[128 * ASTR];
    __shared__ __align__(16) uint16_t sAlo[128 * ASTR];
    __shared__ __align__(16) uint16_t sBhi[128 * ASTR];
    __shared__ __align__(16) uint16_t sBlo[128 * ASTR];

    int tid = threadIdx.x, wid = tid >> 5, lane = tid & 31;
    int wm = wid & 1;
    int wn = wid >> 1;
    int bm0 = blockIdx.y * 128;
    int bn0 = blockIdx.x * 128;

    uint32_t ahi_b = smem_cast(sAhi), alo_b = smem_cast(sAlo);
    uint32_t bhi_b = smem_cast(sBhi), blo_b = smem_cast(sBlo);

    float acc[4][4][4];
#pragma unroll
    for (int i = 0; i < 4; i++)
#pragma unroll
        for (int j = 0; j < 4; j++)
#pragma unroll
            for (int r = 0; r < 4; r++) acc[i][j][r] = 0.f;

    for (int s = 0; s < Cc / 32; s++) {
        int k0 = s * 32;
        // register-stage this stage's global data before the barrier
        float4 bv[4];
#pragma unroll
        for (int i = 0; i < 4; i++) {
            int idx = tid + 256 * i;
            int row = idx >> 3, c4 = idx & 7;
            bv[i] = *(const float4*)(Bm + (size_t)(bn0 + row) * Cc + k0 + c4 * 4);
        }
        uint4 xa[2], xl[2];
        float4 av[4];
        if (MODE == 0) {
            const uint16_t* xhi = (const uint16_t*)g_obuf;
            const uint16_t* xlo = (const uint16_t*)(g_obuf + (size_t)XELEMS * 2);
#pragma unroll
            for (int i = 0; i < 2; i++) {
                int idx = tid + 256 * i;
                int row = idx >> 2, c = idx & 3;
                size_t ga = (size_t)(bm0 + row) * Cc + k0 + c * 8;
                xa[i] = *(const uint4*)(xhi + ga);
                xl[i] = *(const uint4*)(xlo + ga);
            }
        } else {
            const float* Af = (const float*)g_obuf;
#pragma unroll
            for (int i = 0; i < 4; i++) {
                int idx = tid + 256 * i;
                int row = idx >> 3, c4 = idx & 7;
                av[i] = *(const float4*)(Af + (size_t)(bm0 + row) * Cc + k0 + c4 * 4);
            }
        }
        __syncthreads();   // prior stage's MMA reads complete before smem overwrite

        // B tile: fp32 -> hi/lo conversion into smem
#pragma unroll
        for (int i = 0; i < 4; i++) {
            int idx = tid + 256 * i;
            int row = idx >> 3, c4 = idx & 7;
            int base = row * ASTR + c4 * 4;
            float vb4[4] = { bv[i].x, bv[i].y, bv[i].z, bv[i].w };
#pragma unroll
            for (int e = 0; e < 4; e++) {
                __nv_bfloat16 hh = __float2bfloat16(vb4[e]);
                __nv_bfloat16 ll = __float2bfloat16(vb4[e] - __bfloat162float(hh));
                sBhi[base + e] = *(uint16_t*)&hh;
                sBlo[base + e] = *(uint16_t*)&ll;
            }
        }
        // A tile
        if (MODE == 0) {
#pragma unroll
            for (int i = 0; i < 2; i++) {
                int idx = tid + 256 * i;
                int row = idx >> 2, c = idx & 3;
                int off = row * ASTR + c * 8;
                *(uint4*)&sAhi[off] = xa[i];
                *(uint4*)&sAlo[off] = xl[i];
            }
        } else {
#pragma unroll
            for (int i = 0; i < 4; i++) {
                int idx = tid + 256 * i;
                int row = idx >> 3, c4 = idx & 7;
                int base = row * ASTR + c4 * 4;
                float va4[4] = { av[i].x, av[i].y, av[i].z, av[i].w };
#pragma unroll
                for (int e = 0; e < 4; e++) {
                    __nv_bfloat16 hh = __float2bfloat16(va4[e]);
                    __nv_bfloat16 ll = __float2bfloat16(va4[e] - __bfloat162float(hh));
                    sAhi[base + e] = *(uint16_t*)&hh;
                    sAlo[base + e] = *(uint16_t*)&ll;
                }
            }
        }
        __syncthreads();

#pragma unroll
        for (int ks = 0; ks < 2; ks++) {
            uint32_t ah[4][4], al[4][4], bh[2][4], bl[2][4];
            {
                int r = wm * 64 + (lane & 15);
                uint32_t off = (uint32_t)(r * 80 + ks * 32 + ((lane >> 4) << 4));
#pragma unroll
                for (int mf = 0; mf < 4; mf++) {
                    ldm_x4(ah[mf], ahi_b + off + mf * 16 * 80);
                    ldm_x4(al[mf], alo_b + off + mf * 16 * 80);
                }
            }
            {
                int grp = lane >> 3;
                int nr = wn * 32 + ((grp >> 1) << 3) + (lane & 7);
                uint32_t off = (uint32_t)(nr * 80 + ks * 32 + ((grp & 1) << 4));
#pragma unroll
                for (int np = 0; np < 2; np++) {
                    ldm_x4(bh[np], bhi_b + off + np * 16 * 80);
                    ldm_x4(bl[np], blo_b + off + np * 16 * 80);
                }
            }
#pragma unroll
            for (int mf = 0; mf < 4; mf++)
#pragma unroll
                for (int nf = 0; nf < 4; nf++) {
                    const uint32_t* bhp = &bh[nf >> 1][(nf & 1) * 2];
                    const uint32_t* blp = &bl[nf >> 1][(nf & 1) * 2];
                    hmma(acc[mf][nf], ah[mf], bhp);
                    hmma(acc[mf][nf], ah[mf], blp);
                    hmma(acc[mf][nf], al[mf], bhp);
                }
        }
    }

    // ----- epilogue -----
#pragma unroll
    for (int mf = 0; mf < 4; mf++) {
#pragma unroll
        for (int nf = 0; nf < 4; nf++) {
#pragma unroll
            for (int half = 0; half < 2; half++) {
                int row = bm0 + wm * 64 + mf * 16 + (lane >> 2) + half * 8;
                int col = bn0 + wn * 32 + nf * 8 + (lane & 3) * 2;
                float v0 = acc[mf][nf][half * 2];
                float v1 = acc[mf][nf][half * 2 + 1];
                if (MODE == 0) {
                    int b_ = row >> 11;
                    int n_ = row & 2047;
                    int which = col / Cc;
                    int rem = col - which * Cc;
                    int h_ = rem >> 6;
                    int d_ = rem & 63;
                    size_t idx = (((size_t)(b_ * NH + h_) * Nn + n_) << 6) + d_;
                    uint16_t* hiA;
                    uint16_t* loA;
                    // Q scale folds 1/sqrt(64) AND log2(e): attention uses ex2 directly
                    if (which == 0) { v0 *= 0.18033688f; v1 *= 0.18033688f; hiA = g_qhi; loA = g_qlo; }
                    else if (which == 1) { hiA = g_khi; loA = g_klo; }
                    else { hiA = g_vhi; loA = g_vlo; }
                    uint32_t hi, lo;
                    bsplit2(v0, v1, hi, lo);
                    *(uint32_t*)&hiA[idx] = hi;
                    *(uint32_t*)&loA[idx] = lo;
                } else {
                    float* dst = Cout + (size_t)row * Cc + col;
                    *(float2*)dst = make_float2(v0 + bias[col], v1 + bias[col + 1]);
                }
            }
        }
    }
}

// ========== tensor-core flash attention with on-the-fly topo/wind bias ==========
// exp2-domain math: dot2 = log2(e)/8 * (q.k) comes straight out of the MMA
// (scale folded into stored Q). Bias term:
//   sb2 = max(cA * relu(ej - ei) * mod, -10*log2(e)),  cA = -alpha*log2(e)/1000
//   mod = 1 - beta / (1 + exp2(7.2135 - 0.72135*(wi + wj)))
// K/V tiles are register-prefetched one j-tile ahead of the smem commit so the
// global-load latency sits entirely under the previous tile's MMA work.
__global__ void __launch_bounds__(256)
attn_mma(const float* __restrict__ elev,
         const float* __restrict__ alpha_p, const float* __restrict__ beta_p) {
    __shared__ __align__(16) uint16_t sbuf[18432];
    __shared__ float ejs[64], wjs[64];

    int tid = threadIdx.x, w = tid >> 5, L = tid & 31;
    int i0 = blockIdx.x * 128, bh = blockIdx.y;
    int b = bh / NH, h = bh - b * NH;
    float alpha = *alpha_p, beta = *beta_p;
    float cA = alpha * -1.44269504e-3f;
    uint32_t sb32 = smem_cast(sbuf);
    float* g_o = (float*)g_obuf;
    bool is_ew = (tid < 64);   // thread stages one ejs/wjs element

    const uint4* kp0 = (const uint4*)(g_khi + ((size_t)bh * Nn) * HD);
    const uint4* kp1 = (const uint4*)(g_klo + ((size_t)bh * Nn) * HD);
    const uint4* vp0 = (const uint4*)(g_vhi + ((size_t)bh * Nn) * HD);
    const uint4* vp1 = (const uint4*)(g_vlo + ((size_t)bh * Nn) * HD);

    // prefetch j-tile 0 into registers
    uint4 pf[8];
    float pe = 0.f, pwv = 0.f;
#pragma unroll
    for (int it = 0; it < 8; it++) {
        int id = tid + 256 * it;
        int arr = id >> 9, rid = (id >> 3) & 63, c = id & 7;
        const uint4* sp = (arr == 0) ? kp0 : (arr == 1) ? kp1 : (arr == 2) ? vp0 : vp1;
        pf[it] = sp[rid * 8 + c];
    }
    if (is_ew) {
        pe = elev[b * Nn + tid];
        pwv = g_ws[b * Nn + tid];
    }

    // stage Q tile (hi/lo) through smem and pull a-fragments
    {
        const uint4* q0 = (const uint4*)(g_qhi + ((size_t)bh * Nn + i0) * HD);
        const uint4* q1 = (const uint4*)(g_qlo + ((size_t)bh * Nn + i0) * HD);
#pragma unroll
        for (int it = 0; it < 8; it++) {
            int id = tid + 256 * it;
            int arr = id >> 10, rid = (id >> 3) & 127, c = id & 7;
            uint4 vv = (arr == 0) ? q0[rid * 8 + c] : q1[rid * 8 + c];
            *(uint4*)&sbuf[arr * 9216 + rid * 72 + c * 8] = vv;
        }
    }
    __syncthreads();
    uint32_t qh[4][4], ql[4][4];
#pragma unroll
    for (int kc = 0; kc < 4; kc++) {
        uint32_t off = (uint32_t)(((16 * w + (L & 15)) * 72 + kc * 16 + ((L >> 4) << 3)) * 2);
        ldm_x4(qh[kc], sb32 + off);
        ldm_x4(ql[kc], sb32 + 18432 + off);
    }

    int r0 = i0 + 16 * w + (L >> 2);
    float ei0 = elev[b * Nn + r0],     ei1 = elev[b * Nn + r0 + 8];
    float wi0s = 0.72134752f * g_ws[b * Nn + r0];
    float wi1s = 0.72134752f * g_ws[b * Nn + r0 + 8];

    float o[8][4];
#pragma unroll
    for (int i = 0; i < 8; i++)
#pragma unroll
        for (int j = 0; j < 4; j++) o[i][j] = 0.f;
    float l0 = 0.f, l1 = 0.f;

    for (int jt = 0; jt < Nn / 64; jt++) {
        __syncthreads();   // Q-frag reads / previous tile's MMA complete

        // commit prefetched K/V tile + e/w vectors to smem
#pragma unroll
        for (int it = 0; it < 8; it++) {
            int id = tid + 256 * it;
            int arr = id >> 9, rid = (id >> 3) & 63, c = id & 7;
            *(uint4*)&sbuf[arr * 4608 + rid * 72 + c * 8] = pf[it];
        }
        if (is_ew) {
            ejs[tid] = pe;
            wjs[tid] = fmaf(-0.72134752f, pwv, 7.21347522f);
        }

        // prefetch next tile; loads retire under this tile's MMA work
        if (jt + 1 < Nn / 64) {
            int jchunk = (jt + 1) * 64 * 8;
#pragma unroll
            for (int it = 0; it < 8; it++) {
                int id = tid + 256 * it;
                int arr = id >> 9, rid = (id >> 3) & 63, c = id & 7;
                const uint4* sp = (arr == 0) ? kp0 : (arr == 1) ? kp1 : (arr == 2) ? vp0 : vp1;
                pf[it] = sp[jchunk + rid * 8 + c];
            }
            if (is_ew) {
                pe = elev[b * Nn + (jt + 1) * 64 + tid];
                pwv = g_ws[b * Nn + (jt + 1) * 64 + tid];
            }
        }
        __syncthreads();

        float sc[8][4];
#pragma unroll
        for (int i = 0; i < 8; i++)
#pragma unroll
            for (int j = 0; j < 4; j++) sc[i][j] = 0.f;

        // QK^T (result already in exp2 domain via folded Q scale)
        int grp = L >> 3;
#pragma unroll
        for (int kc = 0; kc < 4; kc++) {
#pragma unroll
            for (int nf2 = 0; nf2 < 4; nf2++) {
                uint32_t off = (uint32_t)(((nf2 * 16 + (grp >> 1) * 8 + (L & 7)) * 72
                                          + kc * 16 + (grp & 1) * 8) * 2);
                uint32_t kh2[4], kl2[4];
                ldm_x4(kh2, sb32 + off);
                ldm_x4(kl2, sb32 + 9216 + off);
                hmma(sc[nf2 * 2],     qh[kc], &kh2[0]);
                hmma(sc[nf2 * 2],     qh[kc], &kl2[0]);
                hmma(sc[nf2 * 2],     ql[kc], &kh2[0]);
                hmma(sc[nf2 * 2 + 1], qh[kc], &kh2[2]);
                hmma(sc[nf2 * 2 + 1], qh[kc], &kl2[2]);
                hmma(sc[nf2 * 2 + 1], ql[kc], &kh2[2]);
            }
        }

        // bias + exp2 (strength-reduced)
#pragma unroll
        for (int nf = 0; nf < 8; nf++) {
            int jl = nf * 8 + (L & 3) * 2;
            float e0 = ejs[jl], e1 = ejs[jl + 1];
            float x0 = wjs[jl], x1 = wjs[jl + 1];
            float r00 = fmaxf(e0 - ei0, 0.f) * cA;
            float r01 = fmaxf(e1 - ei0, 0.f) * cA;
            float r10 = fmaxf(e0 - ei1, 0.f) * cA;
            float r11 = fmaxf(e1 - ei1, 0.f) * cA;
            float m00 = fmaf(-beta, fast_rcp(1.f + fast_ex2(x0 - wi0s)), 1.f);
            float m01 = fmaf(-beta, fast_rcp(1.f + fast_ex2(x1 - wi0s)), 1.f);
            float m10 = fmaf(-beta, fast_rcp(1.f + fast_ex2(x0 - wi1s)), 1.f);
            float m11 = fmaf(-beta, fast_rcp(1.f + fast_ex2(x1 - wi1s)), 1.f);
            sc[nf][0] = fast_ex2(sc[nf][0] + fmaxf(r00 * m00, -14.4269504f));
            sc[nf][1] = fast_ex2(sc[nf][1] + fmaxf(r01 * m01, -14.4269504f));
            sc[nf][2] = fast_ex2(sc[nf][2] + fmaxf(r10 * m10, -14.4269504f));
            sc[nf][3] = fast_ex2(sc[nf][3] + fmaxf(r11 * m11, -14.4269504f));
            l0 += sc[nf][0] + sc[nf][1];
            l1 += sc[nf][2] + sc[nf][3];
        }

        // P @ V
#pragma unroll
        for (int jc = 0; jc < 4; jc++) {
            uint32_t phi[4], plo[4];
            bsplit2(sc[2 * jc][0],     sc[2 * jc][1],     phi[0], plo[0]);
            bsplit2(sc[2 * jc][2],     sc[2 * jc][3],     phi[1], plo[1]);
            bsplit2(sc[2 * jc + 1][0], sc[2 * jc + 1][1], phi[2], plo[2]);
            bsplit2(sc[2 * jc + 1][2], sc[2 * jc + 1][3], phi[3], plo[3]);
#pragma unroll
            for (int nd2 = 0; nd2 < 4; nd2++) {
                uint32_t off = (uint32_t)(((jc * 16 + (grp & 1) * 8 + (L & 7)) * 72
                                          + nd2 * 16 + (grp >> 1) * 8) * 2);
                uint32_t vh2[4], vl2[4];
                ldm_x4t(vh2, sb32 + 18432 + off);
                ldm_x4t(vl2, sb32 + 27648 + off);
                hmma(o[nd2 * 2],     phi, &vh2[0]);
                hmma(o[nd2 * 2],     phi, &vl2[0]);
                hmma(o[nd2 * 2],     plo, &vh2[0]);
                hmma(o[nd2 * 2 + 1], phi, &vh2[2]);
                hmma(o[nd2 * 2 + 1], phi, &vl2[2]);
                hmma(o[nd2 * 2 + 1], plo, &vh2[2]);
            }
        }
    }

    // row-sum reduce across the quad and normalize
    l0 += __shfl_xor_sync(0xffffffffu, l0, 1);
    l0 += __shfl_xor_sync(0xffffffffu, l0, 2);
    l1 += __shfl_xor_sync(0xffffffffu, l1, 1);
    l1 += __shfl_xor_sync(0xffffffffu, l1, 2);
    float inv0 = 1.f / l0, inv1 = 1.f / l1;

#pragma unroll
    for (int nf = 0; nf < 8; nf++) {
        int d = h * 64 + nf * 8 + (L & 3) * 2;
        *(float2*)&g_o[((size_t)(b * Nn + r0)) * Cc + d] =
            make_float2(o[nf][0] * inv0, o[nf][1] * inv0);
        *(float2*)&g_o[((size_t)(b * Nn + r0 + 8)) * Cc + d] =
            make_float2(o[nf][2] * inv1, o[nf][3] * inv1);
    }
}

extern "C" void kernel_launch(void* const* d_in, const int* in_sizes, int n_in,
                              void* d_out, int out_size) {
    const float* x     = (const float*)d_in[0];
    const float* elev  = (const float*)d_in[1];
    const float* u     = (const float*)d_in[2];
    const float* v     = (const float*)d_in[3];
    const float* Wqkv  = (const float*)d_in[4];
    const float* Wproj = (const float*)d_in[5];
    const float* bproj = (const float*)d_in[6];
    const float* alpha = (const float*)d_in[7];
    const float* beta  = (const float*)d_in[8];
    float* out = (float*)d_out;

    (void)in_sizes; (void)n_in; (void)out_size;

    // 1. wind strength (2x2 avg pool of |wind|)
    wind_kernel<<<(Bb * Nn + 255) / 256, 256>>>(u, v);

    // 2. pre-split x into phase-1 of the aliased buffer
    split_x_kernel<<<(XELEMS / 4 + 255) / 256, 256>>>(x);

    // 3. QKV projection (A = pre-split copies; B converted in-kernel)
    {
        dim3 grid(3 * Cc / 128, (Bb * Nn) / 128);   // (18, 32)
        mma_gemm<0><<<grid, 256>>>(Wqkv, nullptr, nullptr);
    }

    // 4. flash attention (prefetch-pipelined, exp2-domain bias)
    {
        dim3 grid(Nn / 128, Bb * NH);               // (16, 24)
        attn_mma<<<grid, 256>>>(elev, alpha, beta);
    }

    // 5. output projection (+bias) into d_out
    {
        dim3 grid(Cc / 128, (Bb * Nn) / 128);       // (6, 32)
        mma_gemm<1><<<grid, 256>>>(Wproj, bproj, out);
    }
}

// round 16
// speedup vs baseline: 1.0978x; 1.0665x over previous
#include <cuda_runtime.h>
#include <cuda_bf16.h>
#include <cstdint>
#include <math.h>

// Problem shape constants
#define Bb   2
#define Nn   2048
#define Cc   768
#define NH   12
#define HD   64
#define HW   64
#define WW   128

// ========== mma.sync / ldmatrix wrappers (sm_80+ base ISA, valid on sm_100) ==========
__device__ __forceinline__ uint32_t smem_cast(const void* p) {
    uint32_t a;
    asm("{ .reg .u64 t; cvta.to.shared.u64 t, %1; cvt.u32.u64 %0, t; }" : "=r"(a) : "l"(p));
    return a;
}
__device__ __forceinline__ void ldm_x4(uint32_t* r, uint32_t addr) {
    asm volatile("ldmatrix.sync.aligned.m8n8.x4.shared.b16 {%0,%1,%2,%3}, [%4];"
                 : "=r"(r[0]), "=r"(r[1]), "=r"(r[2]), "=r"(r[3]) : "r"(addr));
}
__device__ __forceinline__ void ldm_x4t(uint32_t* r, uint32_t addr) {
    asm volatile("ldmatrix.sync.aligned.m8n8.x4.trans.shared.b16 {%0,%1,%2,%3}, [%4];"
                 : "=r"(r[0]), "=r"(r[1]), "=r"(r[2]), "=r"(r[3]) : "r"(addr));
}
__device__ __forceinline__ void hmma(float* c, const uint32_t* a, const uint32_t* b) {
    asm volatile(
        "mma.sync.aligned.m16n8k16.row.col.f32.bf16.bf16.f32 "
        "{%0,%1,%2,%3}, {%4,%5,%6,%7}, {%8,%9}, {%0,%1,%2,%3};"
        : "+f"(c[0]), "+f"(c[1]), "+f"(c[2]), "+f"(c[3])
        : "r"(a[0]), "r"(a[1]), "r"(a[2]), "r"(a[3]), "r"(b[0]), "r"(b[1]));
}
// 2-term bf16 split of an fp32 pair, packed into two b32 lanes
__device__ __forceinline__ void bsplit2(float x, float y, uint32_t& hi, uint32_t& lo) {
    __nv_bfloat16 hx = __float2bfloat16(x), hy = __float2bfloat16(y);
    float rx = x - __bfloat162float(hx), ry = y - __bfloat162float(hy);
    __nv_bfloat16 ex = __float2bfloat16(rx), ey = __float2bfloat16(ry);
    hi = (uint32_t)(*(uint16_t*)&hx) | ((uint32_t)(*(uint16_t*)&hy) << 16);
    lo = (uint32_t)(*(uint16_t*)&ex) | ((uint32_t)(*(uint16_t*)&ey) << 16);
}
__device__ __forceinline__ float fast_ex2(float x) {
    float r; asm("ex2.approx.f32 %0, %1;" : "=f"(r) : "f"(x)); return r;
}
__device__ __forceinline__ float fast_rcp(float x) {
    float r; asm("rcp.approx.f32 %0, %1;" : "=f"(r) : "f"(x)); return r;
}
__device__ __forceinline__ void cpa16(uint32_t s, const void* g) {
    asm volatile("cp.async.cg.shared.global [%0], [%1], 16;" :: "r"(s), "l"(g));
}
#define CPC()  asm volatile("cp.async.commit_group;" ::: "memory")
#define CPW1() asm volatile("cp.async.wait_group 1;" ::: "memory")
#define CPW0() asm volatile("cp.async.wait_group 0;" ::: "memory")

// ========== device scratch: ~50.3 MB (well inside the confirmed globals budget) ======
__device__ uint16_t g_qhi[Bb * NH * Nn * HD];   // bf16; 0.125*log2(e) folded in
__device__ uint16_t g_qlo[Bb * NH * Nn * HD];
__device__ uint16_t g_khi[Bb * NH * Nn * HD];
__device__ uint16_t g_klo[Bb * NH * Nn * HD];
__device__ uint16_t g_vhi[Bb * NH * Nn * HD];
__device__ uint16_t g_vlo[Bb * NH * Nn * HD];
// Time-multiplexed buffer. Phase 1 (steps 2-3): pre-split x as [bf16 hi | bf16 lo].
// Phase 2 (steps 4-5): fp32 attention output o. Lifetimes disjoint; regenerated
// on every graph replay, so results are replay-deterministic.
#define XELEMS (Bb * Nn * Cc)
__device__ __align__(16) unsigned char g_obuf[(size_t)XELEMS * 4];
__device__ float g_ws[Bb * Nn];

// ========== wind strength: 2x2 avg-pool of wind magnitude ==========
__global__ void wind_kernel(const float* __restrict__ u, const float* __restrict__ v) {
    int idx = blockIdx.x * blockDim.x + threadIdx.x;
    if (idx >= Bb * Nn) return;
    int b = idx / Nn, n = idx - b * Nn;
    int ph = n >> 6, pw = n & 63;
    const float* ub = u + b * HW * WW;
    const float* vb = v + b * HW * WW;
    float s = 0.f;
#pragma unroll
    for (int di = 0; di < 2; di++)
#pragma unroll
        for (int dj = 0; dj < 2; dj++) {
            int r = 2 * ph + di, c = 2 * pw + dj;
            float uu = ub[r * WW + c];
            float vv = vb[r * WW + c];
            s += sqrtf(uu * uu + vv * vv + 1e-8f);
        }
    g_ws[idx] = 0.25f * s;
}

// ========== x -> bf16 hi/lo, written into phase-1 of g_obuf ==========
__global__ void split_x_kernel(const float* __restrict__ src) {
    int i = blockIdx.x * blockDim.x + threadIdx.x;
    if (i >= XELEMS / 4) return;
    uint16_t* hi = (uint16_t*)g_obuf;
    uint16_t* lo = (uint16_t*)(g_obuf + (size_t)XELEMS * 2);
    float4 v = ((const float4*)src)[i];
    uint32_t h0, l0, h1, l1;
    bsplit2(v.x, v.y, h0, l0);
    bsplit2(v.z, v.w, h1, l1);
    ((uint2*)hi)[i] = make_uint2(h0, h1);
    ((uint2*)lo)[i] = make_uint2(l0, l1);
}

// ========== bf16-split tensor-core GEMM, C = A @ B^T (R15-proven, unchanged) ==========
#define ASTR 40   // smem row stride in bf16 elems (80 B) -> conflict-free ldmatrix

template <int MODE>
__global__ void __launch_bounds__(256, 2)
mma_gemm(const float* __restrict__ Bm, const float* __restrict__ bias,
         float* __restrict__ Cout) {
    __shared__ __align__(16) uint16_t sAhi[128 * ASTR];
    __shared__ __align__(16) uint16_t sAlo[128 * ASTR];
    __shared__ __align__(16) uint16_t sBhi[128 * ASTR];
    __shared__ __align__(16) uint16_t sBlo[128 * ASTR];

    int tid = threadIdx.x, wid = tid >> 5, lane = tid & 31;
    int wm = wid & 1;
    int wn = wid >> 1;
    int bm0 = blockIdx.y * 128;
    int bn0 = blockIdx.x * 128;

    uint32_t ahi_b = smem_cast(sAhi), alo_b = smem_cast(sAlo);
    uint32_t bhi_b = smem_cast(sBhi), blo_b = smem_cast(sBlo);

    float acc[4][4][4];
#pragma unroll
    for (int i = 0; i < 4; i++)
#pragma unroll
        for (int j = 0; j < 4; j++)
#pragma unroll
            for (int r = 0; r < 4; r++) acc[i][j][r] = 0.f;

    for (int s = 0; s < Cc / 32; s++) {
        int k0 = s * 32;
        float4 bv[4];
#pragma unroll
        for (int i = 0; i < 4; i++) {
            int idx = tid + 256 * i;
            int row = idx >> 3, c4 = idx & 7;
            bv[i] = *(const float4*)(Bm + (size_t)(bn0 + row) * Cc + k0 + c4 * 4);
        }
        uint4 xa[2], xl[2];
        float4 av[4];
        if (MODE == 0) {
            const uint16_t* xhi = (const uint16_t*)g_obuf;
            const uint16_t* xlo = (const uint16_t*)(g_obuf + (size_t)XELEMS * 2);
#pragma unroll
            for (int i = 0; i < 2; i++) {
                int idx = tid + 256 * i;
                int row = idx >> 2, c = idx & 3;
                size_t ga = (size_t)(bm0 + row) * Cc + k0 + c * 8;
                xa[i] = *(const uint4*)(xhi + ga);
                xl[i] = *(const uint4*)(xlo + ga);
            }
        } else {
            const float* Af = (const float*)g_obuf;
#pragma unroll
            for (int i = 0; i < 4; i++) {
                int idx = tid + 256 * i;
                int row = idx >> 3, c4 = idx & 7;
                av[i] = *(const float4*)(Af + (size_t)(bm0 + row) * Cc + k0 + c4 * 4);
            }
        }
        __syncthreads();

#pragma unroll
        for (int i = 0; i < 4; i++) {
            int idx = tid + 256 * i;
            int row = idx >> 3, c4 = idx & 7;
            int base = row * ASTR + c4 * 4;
            float vb4[4] = { bv[i].x, bv[i].y, bv[i].z, bv[i].w };
#pragma unroll
            for (int e = 0; e < 4; e++) {
                __nv_bfloat16 hh = __float2bfloat16(vb4[e]);
                __nv_bfloat16 ll = __float2bfloat16(vb4[e] - __bfloat162float(hh));
                sBhi[base + e] = *(uint16_t*)&hh;
                sBlo[base + e] = *(uint16_t*)&ll;
            }
        }
        if (MODE == 0) {
#pragma unroll
            for (int i = 0; i < 2; i++) {
                int idx = tid + 256 * i;
                int row = idx >> 2, c = idx & 3;
                int off = row * ASTR + c * 8;
                *(uint4*)&sAhi[off] = xa[i];
                *(uint4*)&sAlo[off] = xl[i];
            }
        } else {
#pragma unroll
            for (int i = 0; i < 4; i++) {
                int idx = tid + 256 * i;
                int row = idx >> 3, c4 = idx & 7;
                int base = row * ASTR + c4 * 4;
                float va4[4] = { av[i].x, av[i].y, av[i].z, av[i].w };
#pragma unroll
                for (int e = 0; e < 4; e++) {
                    __nv_bfloat16 hh = __float2bfloat16(va4[e]);
                    __nv_bfloat16 ll = __float2bfloat16(va4[e] - __bfloat162float(hh));
                    sAhi[base + e] = *(uint16_t*)&hh;
                    sAlo[base + e] = *(uint16_t*)&ll;
                }
            }
        }
        __syncthreads();

#pragma unroll
        for (int ks = 0; ks < 2; ks++) {
            uint32_t ah[4][4], al[4][4], bh[2][4], bl[2][4];
            {
                int r = wm * 64 + (lane & 15);
                uint32_t off = (uint32_t)(r * 80 + ks * 32 + ((lane >> 4) << 4));
#pragma unroll
                for (int mf = 0; mf < 4; mf++) {
                    ldm_x4(ah[mf], ahi_b + off + mf * 16 * 80);
                    ldm_x4(al[mf], alo_b + off + mf * 16 * 80);
                }
            }
            {
                int grp = lane >> 3;
                int nr = wn * 32 + ((grp >> 1) << 3) + (lane & 7);
                uint32_t off = (uint32_t)(nr * 80 + ks * 32 + ((grp & 1) << 4));
#pragma unroll
                for (int np = 0; np < 2; np++) {
                    ldm_x4(bh[np], bhi_b + off + np * 16 * 80);
                    ldm_x4(bl[np], blo_b + off + np * 16 * 80);
                }
            }
#pragma unroll
            for (int mf = 0; mf < 4; mf++)
#pragma unroll
                for (int nf = 0; nf < 4; nf++) {
                    const uint32_t* bhp = &bh[nf >> 1][(nf & 1) * 2];
                    const uint32_t* blp = &bl[nf >> 1][(nf & 1) * 2];
                    hmma(acc[mf][nf], ah[mf], bhp);
                    hmma(acc[mf][nf], ah[mf], blp);
                    hmma(acc[mf][nf], al[mf], bhp);
                }
        }
    }

    // ----- epilogue -----
#pragma unroll
    for (int mf = 0; mf < 4; mf++) {
#pragma unroll
        for (int nf = 0; nf < 4; nf++) {
#pragma unroll
            for (int half = 0; half < 2; half++) {
                int row = bm0 + wm * 64 + mf * 16 + (lane >> 2) + half * 8;
                int col = bn0 + wn * 32 + nf * 8 + (lane & 3) * 2;
                float v0 = acc[mf][nf][half * 2];
                float v1 = acc[mf][nf][half * 2 + 1];
                if (MODE == 0) {
                    int b_ = row >> 11;
                    int n_ = row & 2047;
                    int which = col / Cc;
                    int rem = col - which * Cc;
                    int h_ = rem >> 6;
                    int d_ = rem & 63;
                    size_t idx = (((size_t)(b_ * NH + h_) * Nn + n_) << 6) + d_;
                    uint16_t* hiA;
                    uint16_t* loA;
                    // Q scale folds 1/sqrt(64) AND log2(e): attention uses ex2 directly
                    if (which == 0) { v0 *= 0.18033688f; v1 *= 0.18033688f; hiA = g_qhi; loA = g_qlo; }
                    else if (which == 1) { hiA = g_khi; loA = g_klo; }
                    else { hiA = g_vhi; loA = g_vlo; }
                    uint32_t hi, lo;
                    bsplit2(v0, v1, hi, lo);
                    *(uint32_t*)&hiA[idx] = hi;
                    *(uint32_t*)&loA[idx] = lo;
                } else {
                    float* dst = Cout + (size_t)row * Cc + col;
                    *(float2*)dst = make_float2(v0 + bias[col], v1 + bias[col + 1]);
                }
            }
        }
    }
}

// ========== tensor-core flash attention, 2 CTAs/SM edition ==========
// Register diet vs R15: K/V prefetch moved to cp.async double-buffered dynamic smem
// (frees 32 regs), Q kept resident in smem and re-ldsm'd per kc (frees 32 regs).
// Dynamic smem layout (bytes): Qhi [0,18432) | Qlo [18432,36864)
//   | KVbuf0 [36864,73728) | KVbuf1 [73728,110592)
// Each KV buf: khi +0 | klo +9216 | vhi +18432 | vlo +27648 (bytes within buf).
__global__ void __launch_bounds__(256, 2)
attn_mma(const float* __restrict__ elev,
         const float* __restrict__ alpha_p, const float* __restrict__ beta_p) {
    extern __shared__ __align__(16) uint16_t dsm[];
    __shared__ float ejs[64], wjs[64];

    int tid = threadIdx.x, w = tid >> 5, L = tid & 31;
    int i0 = blockIdx.x * 128, bh = blockIdx.y;
    int b = bh / NH, h = bh - b * NH;
    float alpha = *alpha_p, beta = *beta_p;
    float cA = alpha * -1.44269504e-3f;
    uint32_t sb = smem_cast(dsm);
    float* g_o = (float*)g_obuf;
    bool is_ew = (tid < 64);

    const uint4* kp0 = (const uint4*)(g_khi + ((size_t)bh * Nn) * HD);
    const uint4* kp1 = (const uint4*)(g_klo + ((size_t)bh * Nn) * HD);
    const uint4* vp0 = (const uint4*)(g_vhi + ((size_t)bh * Nn) * HD);
    const uint4* vp1 = (const uint4*)(g_vlo + ((size_t)bh * Nn) * HD);

    // issue tile 0 cp.async into KV buf 0
#pragma unroll
    for (int it = 0; it < 8; it++) {
        int id = tid + 256 * it;
        int arr = id >> 9, rid = (id >> 3) & 63, c = id & 7;
        const uint4* sp = (arr == 0) ? kp0 : (arr == 1) ? kp1 : (arr == 2) ? vp0 : vp1;
        uint32_t dst = sb + 36864u + (uint32_t)(arr * 4608 + rid * 72 + c * 8) * 2;
        cpa16(dst, sp + rid * 8 + c);
    }
    CPC();

    float pe = 0.f, pwv = 0.f;
    if (is_ew) {
        pe = elev[b * Nn + tid];
        pwv = g_ws[b * Nn + tid];
    }

    // stage Q tile (hi/lo) into its resident smem region
    {
        const uint4* q0 = (const uint4*)(g_qhi + ((size_t)bh * Nn + i0) * HD);
        const uint4* q1 = (const uint4*)(g_qlo + ((size_t)bh * Nn + i0) * HD);
#pragma unroll
        for (int it = 0; it < 8; it++) {
            int id = tid + 256 * it;
            int arr = id >> 10, rid = (id >> 3) & 127, c = id & 7;
            uint4 vv = (arr == 0) ? q0[rid * 8 + c] : q1[rid * 8 + c];
            *(uint4*)&dsm[arr * 9216 + rid * 72 + c * 8] = vv;
        }
    }

    int r0 = i0 + 16 * w + (L >> 2);
    float ei0 = elev[b * Nn + r0],     ei1 = elev[b * Nn + r0 + 8];
    float wi0s = 0.72134752f * g_ws[b * Nn + r0];
    float wi1s = 0.72134752f * g_ws[b * Nn + r0 + 8];

    float o[8][4];
#pragma unroll
    for (int i = 0; i < 8; i++)
#pragma unroll
        for (int j = 0; j < 4; j++) o[i][j] = 0.f;
    float l0 = 0.f, l1 = 0.f;
    int grp = L >> 3;

    for (int jt = 0; jt < Nn / 64; jt++) {
        __syncthreads();   // prior tile's compute fully done -> both KV buffers free

        if (jt + 1 < Nn / 64) {
            int jchunk = (jt + 1) * 64 * 8;
            uint32_t kvdst = sb + 36864u + (uint32_t)(((jt + 1) & 1) * 36864);
#pragma unroll
            for (int it = 0; it < 8; it++) {
                int id = tid + 256 * it;
                int arr = id >> 9, rid = (id >> 3) & 63, c = id & 7;
                const uint4* sp = (arr == 0) ? kp0 : (arr == 1) ? kp1 : (arr == 2) ? vp0 : vp1;
                cpa16(kvdst + (uint32_t)(arr * 4608 + rid * 72 + c * 8) * 2,
                      sp + jchunk + rid * 8 + c);
            }
            CPC();
            CPW1();   // tile jt's group complete; tile jt+1 stays in flight
        } else {
            CPW0();
        }

        if (is_ew) {
            ejs[tid] = pe;
            wjs[tid] = fmaf(-0.72134752f, pwv, 7.21347522f);
            if (jt + 1 < Nn / 64) {
                pe = elev[b * Nn + (jt + 1) * 64 + tid];
                pwv = g_ws[b * Nn + (jt + 1) * 64 + tid];
            }
        }
        __syncthreads();   // tile jt KV + ejs/wjs (+ Q on jt==0) visible CTA-wide

        uint32_t kvb = sb + 36864u + (uint32_t)((jt & 1) * 36864);

        float sc[8][4];
#pragma unroll
        for (int i = 0; i < 8; i++)
#pragma unroll
            for (int j = 0; j < 4; j++) sc[i][j] = 0.f;

        // QK^T: Q frags re-loaded per kc from resident smem (8 live Q regs, not 32)
#pragma unroll
        for (int kc = 0; kc < 4; kc++) {
            uint32_t qoff = (uint32_t)(((16 * w + (L & 15)) * 72 + kc * 16 + ((L >> 4) << 3)) * 2);
            uint32_t qh4[4], ql4[4];
            ldm_x4(qh4, sb + qoff);
            ldm_x4(ql4, sb + 18432u + qoff);
#pragma unroll
            for (int nf2 = 0; nf2 < 4; nf2++) {
                uint32_t off = (uint32_t)(((nf2 * 16 + (grp >> 1) * 8 + (L & 7)) * 72
                                          + kc * 16 + (grp & 1) * 8) * 2);
                uint32_t kh2[4], kl2[4];
                ldm_x4(kh2, kvb + off);
                ldm_x4(kl2, kvb + 9216u + off);
                hmma(sc[nf2 * 2],     qh4, &kh2[0]);
                hmma(sc[nf2 * 2],     qh4, &kl2[0]);
                hmma(sc[nf2 * 2],     ql4, &kh2[0]);
                hmma(sc[nf2 * 2 + 1], qh4, &kh2[2]);
                hmma(sc[nf2 * 2 + 1], qh4, &kl2[2]);
                hmma(sc[nf2 * 2 + 1], ql4, &kh2[2]);
            }
        }

        // bias + exp2 (strength-reduced)
#pragma unroll
        for (int nf = 0; nf < 8; nf++) {
            int jl = nf * 8 + (L & 3) * 2;
            float e0 = ejs[jl], e1 = ejs[jl + 1];
            float x0 = wjs[jl], x1 = wjs[jl + 1];
            float r00 = fmaxf(e0 - ei0, 0.f) * cA;
            float r01 = fmaxf(e1 - ei0, 0.f) * cA;
            float r10 = fmaxf(e0 - ei1, 0.f) * cA;
            float r11 = fmaxf(e1 - ei1, 0.f) * cA;
            float m00 = fmaf(-beta, fast_rcp(1.f + fast_ex2(x0 - wi0s)), 1.f);
            float m01 = fmaf(-beta, fast_rcp(1.f + fast_ex2(x1 - wi0s)), 1.f);
            float m10 = fmaf(-beta, fast_rcp(1.f + fast_ex2(x0 - wi1s)), 1.f);
            float m11 = fmaf(-beta, fast_rcp(1.f + fast_ex2(x1 - wi1s)), 1.f);
            sc[nf][0] = fast_ex2(sc[nf][0] + fmaxf(r00 * m00, -14.4269504f));
            sc[nf][1] = fast_ex2(sc[nf][1] + fmaxf(r01 * m01, -14.4269504f));
            sc[nf][2] = fast_ex2(sc[nf][2] + fmaxf(r10 * m10, -14.4269504f));
            sc[nf][3] = fast_ex2(sc[nf][3] + fmaxf(r11 * m11, -14.4269504f));
            l0 += sc[nf][0] + sc[nf][1];
            l1 += sc[nf][2] + sc[nf][3];
        }

        // P @ V
#pragma unroll
        for (int jc = 0; jc < 4; jc++) {
            uint32_t phi[4], plo[4];
            bsplit2(sc[2 * jc][0],     sc[2 * jc][1],     phi[0], plo[0]);
            bsplit2(sc[2 * jc][2],     sc[2 * jc][3],     phi[1], plo[1]);
            bsplit2(sc[2 * jc + 1][0], sc[2 * jc + 1][1], phi[2], plo[2]);
            bsplit2(sc[2 * jc + 1][2], sc[2 * jc + 1][3], phi[3], plo[3]);
#pragma unroll
            for (int nd2 = 0; nd2 < 4; nd2++) {
                uint32_t off = (uint32_t)(((jc * 16 + (grp & 1) * 8 + (L & 7)) * 72
                                          + nd2 * 16 + (grp >> 1) * 8) * 2);
                uint32_t vh2[4], vl2[4];
                ldm_x4t(vh2, kvb + 18432u + off);
                ldm_x4t(vl2, kvb + 27648u + off);
                hmma(o[nd2 * 2],     phi, &vh2[0]);
                hmma(o[nd2 * 2],     phi, &vl2[0]);
                hmma(o[nd2 * 2],     plo, &vh2[0]);
                hmma(o[nd2 * 2 + 1], phi, &vh2[2]);
                hmma(o[nd2 * 2 + 1], phi, &vl2[2]);
                hmma(o[nd2 * 2 + 1], plo, &vh2[2]);
            }
        }
    }

    // row-sum reduce across the quad and normalize
    l0 += __shfl_xor_sync(0xffffffffu, l0, 1);
    l0 += __shfl_xor_sync(0xffffffffu, l0, 2);
    l1 += __shfl_xor_sync(0xffffffffu, l1, 1);
    l1 += __shfl_xor_sync(0xffffffffu, l1, 2);
    float inv0 = 1.f / l0, inv1 = 1.f / l1;

#pragma unroll
    for (int nf = 0; nf < 8; nf++) {
        int d = h * 64 + nf * 8 + (L & 3) * 2;
        *(float2*)&g_o[((size_t)(b * Nn + r0)) * Cc + d] =
            make_float2(o[nf][0] * inv0, o[nf][1] * inv0);
        *(float2*)&g_o[((size_t)(b * Nn + r0 + 8)) * Cc + d] =
            make_float2(o[nf][2] * inv1, o[nf][3] * inv1);
    }
}

#define ATTN_SMEM 110592

extern "C" void kernel_launch(void* const* d_in, const int* in_sizes, int n_in,
                              void* d_out, int out_size) {
    const float* x     = (const float*)d_in[0];
    const float* elev  = (const float*)d_in[1];
    const float* u     = (const float*)d_in[2];
    const float* v     = (const float*)d_in[3];
    const float* Wqkv  = (const float*)d_in[4];
    const float* Wproj = (const float*)d_in[5];
    const float* bproj = (const float*)d_in[6];
    const float* alpha = (const float*)d_in[7];
    const float* beta  = (const float*)d_in[8];
    float* out = (float*)d_out;

    (void)in_sizes; (void)n_in; (void)out_size;

    cudaFuncSetAttribute(attn_mma, cudaFuncAttributeMaxDynamicSharedMemorySize, ATTN_SMEM);

    // 1. wind strength (2x2 avg pool of |wind|)
    wind_kernel<<<(Bb * Nn + 255) / 256, 256>>>(u, v);

    // 2. pre-split x into phase-1 of the aliased buffer
    split_x_kernel<<<(XELEMS / 4 + 255) / 256, 256>>>(x);

    // 3. QKV projection (A = pre-split copies; B converted in-kernel)
    {
        dim3 grid(3 * Cc / 128, (Bb * Nn) / 128);   // (18, 32)
        mma_gemm<0><<<grid, 256>>>(Wqkv, nullptr, nullptr);
    }

    // 4. flash attention (cp.async double-buffered, smem-resident Q, 2 CTAs/SM)
    {
        dim3 grid(Nn / 128, Bb * NH);               // (16, 24)
        attn_mma<<<grid, 256, ATTN_SMEM>>>(elev, alpha, beta);
    }

    // 5. output projection (+bias) into d_out
    {
        dim3 grid(Cc / 128, (Bb * Nn) / 128);       // (6, 32)
        mma_gemm<1><<<grid, 256>>>(Wproj, bproj, out);
    }
}